// round 16
// baseline (speedup 1.0000x reference)
#include <cuda_runtime.h>
#include <cuda_fp16.h>
#include <math.h>

typedef __half hf;

#define BB 64
#define TT 512
#define II 256
#define HH 512
#define CC 128

#define NBLK 128
#define NTHR 288          // 8 compute warps + 1 producer warp
#define NCW  256
#define NWAVE (TT + 1)    // 513

#define K0 768
#define K1 1024
#define NSC0 6
#define NSC1 8

// smem layout (bytes)
#define SM_W    0                 // resident W: up to 16 subtiles x 8KB = 128KB
#define SM_RING 131072            // 3 x 16KB X ring (per buf: [t0 Xh 4K|Xl 4K][t1 Xh 4K|Xl 4K])
#define RINGB   16384
#define SM_EXCH 180224            // 4 planes x 64 x EXPITCH x 4B = 34816
#define EXPITCH 34
#define SM_MB   215040            // full[3] @ +0, empty[3] @ +24
#define SMEM_TOTAL 215104

#define SWZ(o) ((o) ^ (((o) >> 3) & 0x70))

// ---------------- device scratch ----------------
__device__ __align__(256) hf g_w0[2048 * K0];
__device__ __align__(256) hf g_w1[2048 * K1];
__device__ __align__(256) hf g_xh[(size_t)BB * TT * II], g_xl[(size_t)BB * TT * II];
__device__ __align__(256) hf g_h0h[8][BB * HH], g_h0l[8][BB * HH];   // 8-deep ring
__device__ __align__(256) hf g_h1h[2][BB * HH], g_h1l[2][BB * HH];
__device__ float g_h1last[BB * HH];
__device__ unsigned g_ctr0, g_ctr1, g_done;   // zero-init; reset at kernel end

// ---------------- primitives ----------------
__device__ __forceinline__ void cp16(unsigned saddr, const void* g) {
    asm volatile("cp.async.cg.shared.global [%0], [%1], 16;\n" :: "r"(saddr), "l"(g) : "memory");
}
__device__ __forceinline__ void cp_commit() {
    asm volatile("cp.async.commit_group;\n" ::: "memory");
}
template <int N> __device__ __forceinline__ void cp_wait() {
    asm volatile("cp.async.wait_group %0;\n" :: "n"(N) : "memory");
}
__device__ __forceinline__ void bar_arrive(unsigned* ctr) {
    unsigned old;
    asm volatile("atom.release.gpu.global.add.u32 %0, [%1], %2;"
                 : "=r"(old) : "l"(ctr), "r"(1u) : "memory");
}
__device__ __forceinline__ void bar_wait(unsigned* ctr, unsigned target) {
    unsigned v;
    do {
        asm volatile("ld.acquire.gpu.global.u32 %0, [%1];" : "=r"(v) : "l"(ctr) : "memory");
    } while (v < target);
}
__device__ __forceinline__ void mbar_init(unsigned a, unsigned cnt) {
    asm volatile("mbarrier.init.shared.b64 [%0], %1;" :: "r"(a), "r"(cnt) : "memory");
}
__device__ __forceinline__ void mbar_arrive_cnt(unsigned a, unsigned cnt) {
    asm volatile("mbarrier.arrive.shared::cta.b64 _, [%0], %1;" :: "r"(a), "r"(cnt) : "memory");
}
__device__ __forceinline__ void mwait(unsigned a, unsigned parity) {
    asm volatile(
        "{\n\t.reg .pred P1;\n\t"
        "WL%=:\n\t"
        "mbarrier.try_wait.parity.acquire.cta.shared::cta.b64 P1, [%0], %1, 0x989680;\n\t"
        "@P1 bra.uni WD%=;\n\t"
        "bra.uni WL%=;\n\t"
        "WD%=:\n\t}"
        :: "r"(a), "r"(parity) : "memory");
}
// .noinc is load-bearing: without it the arrive is paired with a pending-count
// increment and the 32-count init is never consumed -> phase never completes (R14 hang).
__device__ __forceinline__ void cp_mbar_arrive(unsigned a) {
    asm volatile("cp.async.mbarrier.arrive.noinc.shared::cta.b64 [%0];" :: "r"(a) : "memory");
}
__device__ __forceinline__ float sig_(float x)  { return 1.0f / (1.0f + __expf(-x)); }
__device__ __forceinline__ float tanh_(float x) { return 2.0f / (1.0f + __expf(-2.0f * x)) - 1.0f; }

__device__ __forceinline__ void ldsm4(unsigned* r, unsigned addr) {
    asm volatile("ldmatrix.sync.aligned.m8n8.x4.shared.b16 {%0,%1,%2,%3}, [%4];"
                 : "=r"(r[0]), "=r"(r[1]), "=r"(r[2]), "=r"(r[3]) : "r"(addr));
}
__device__ __forceinline__ void mma16816(float* c, const unsigned* a, unsigned b0, unsigned b1) {
    asm volatile(
        "mma.sync.aligned.m16n8k16.row.col.f32.f16.f16.f32 "
        "{%0,%1,%2,%3}, {%4,%5,%6,%7}, {%8,%9}, {%0,%1,%2,%3};"
        : "+f"(c[0]), "+f"(c[1]), "+f"(c[2]), "+f"(c[3])
        : "r"(a[0]), "r"(a[1]), "r"(a[2]), "r"(a[3]), "r"(b0), "r"(b1));
}

// ---------------- tensor compute: one superchunk (K=128), m32 x n32, 2 fp16 terms ------
__device__ __forceinline__ void cchunk(
    unsigned wch, unsigned xch, float acc[2][4][4],
    unsigned kb, unsigned aoff, unsigned boff)
{
    #pragma unroll
    for (int t = 0; t < 2; t++) {
        const unsigned wb = wch + (unsigned)t * 8192u;
        const unsigned xb = xch + (unsigned)t * 8192u;
        unsigned a0[4], a1[4], b0h[4], b1h[4], b0l[4], b1l[4];
        ldsm4(a0, wb + aoff + kb);
        ldsm4(a1, wb + aoff + 2048u + kb);
        ldsm4(b0h, xb + boff + kb);
        ldsm4(b1h, xb + boff + 2048u + kb);
        ldsm4(b0l, xb + 4096u + boff + kb);
        ldsm4(b1l, xb + 4096u + 2048u + boff + kb);
        #pragma unroll
        for (int mi = 0; mi < 2; mi++) {
            const unsigned* a = mi ? a1 : a0;
            mma16816(acc[mi][0], a, b0h[0], b0h[2]);
            mma16816(acc[mi][1], a, b0h[1], b0h[3]);
            mma16816(acc[mi][2], a, b1h[0], b1h[2]);
            mma16816(acc[mi][3], a, b1h[1], b1h[3]);
            mma16816(acc[mi][0], a, b0l[0], b0l[2]);
            mma16816(acc[mi][1], a, b0l[1], b0l[3]);
            mma16816(acc[mi][2], a, b1l[0], b1l[2]);
            mma16816(acc[mi][3], a, b1l[1], b1l[3]);
        }
    }
}

// ---------------- producer: stage one superchunk of X (1024 granules / 32 lanes) -------
__device__ __forceinline__ void pstage(
    unsigned dst, int sc, int layer, int nb, int step, int lane,
    const hf* h0h_, const hf* h0l_, const hf* h1h_, const hf* h1l_)
{
    #pragma unroll 8
    for (int q = 0; q < 32; q++) {
        int g = q * 32 + lane;
        int t = g >> 9, rem9 = g & 511;
        int plane = rem9 >> 8, rem = rem9 & 255;
        int row = rem >> 3, j = rem & 7;
        int rg = nb * 32 + row;
        int k = sc * 128 + t * 64 + j * 8;
        const hf* src;
        if (layer == 0)
            src = (k < II) ? (plane ? g_xl : g_xh) + ((size_t)rg * TT + step) * II + k
                           : (plane ? h0l_ : h0h_) + rg * HH + (k - II);
        else
            src = (k < HH) ? (plane ? h0l_ : h0h_) + rg * HH + k
                           : (plane ? h1l_ : h1h_) + rg * HH + (k - HH);
        cp16(dst + (unsigned)t * 8192u + (unsigned)plane * 4096u
             + SWZ((unsigned)(row * 128 + j * 16)), src);
    }
}

// ---------------- main persistent kernel ----------------
__global__ void __launch_bounds__(NTHR, 1) lstm_mma_kernel(
    const float* __restrict__ b_ih0, const float* __restrict__ b_hh0,
    const float* __restrict__ b_ih1, const float* __restrict__ b_hh1,
    const float* __restrict__ h0g, const float* __restrict__ c0g)
{
    extern __shared__ char smem[];
    const unsigned sbase = (unsigned)__cvta_generic_to_shared(smem);
    float* exch = (float*)(smem + SM_EXCH);

    const int tid = threadIdx.x;
    const int lane = tid & 31, wid = tid >> 5;
    const int blk = blockIdx.x;
    const int layer = blk >> 6;
    const int sub = (blk >> 1) & 31;
    const int nb  = blk & 1;
    const int K = layer ? K1 : K0;
    const int NSC = layer ? NSC1 : NSC0;
    const hf* w = layer ? g_w1 : g_w0;
    unsigned* ctrOwn = layer ? &g_ctr1 : &g_ctr0;

    const unsigned mbF = sbase + SM_MB;        // full[3]
    const unsigned mbE = sbase + SM_MB + 24;   // empty[3]

    if (tid == 0) {
        #pragma unroll
        for (int i = 0; i < 3; i++) { mbar_init(mbF + i * 8, 32); mbar_init(mbE + i * 8, 256); }
    }

    // ---- prologue: W resident load + h/c init (compute threads) ----
    if (tid < NCW) {
        const int nsub = K >> 6;
        for (int idx = tid; idx < nsub * 512; idx += NCW) {
            int s64 = idx >> 9, rem = idx & 511, row = rem >> 3, j = rem & 7;
            const hf* src = w + (size_t)(sub * 64 + row) * K + s64 * 64 + j * 8;
            cp16(sbase + SM_W + (unsigned)s64 * 8192u + SWZ((unsigned)(row * 128 + j * 16)), src);
        }
        cp_commit();
        cp_wait<0>();
        int i = blk * 256 + tid;
        float v0 = h0g[i];
        hf a = __float2half(v0);
        g_h0h[7][i] = a; g_h0l[7][i] = __float2half(v0 - __half2float(a));
        float v1 = h0g[BB * HH + i];
        hf b = __float2half(v1);
        g_h1h[0][i] = b; g_h1l[0][i] = __float2half(v1 - __half2float(b));
    }
    __threadfence();
    __syncthreads();
    if (tid == 0) bar_arrive(ctrOwn);

    if (wid == 8) {
        // =============== PRODUCER WARP ===============
        int pst = 0, pph = 1;
        #pragma unroll 1
        for (int s = 0; s < NWAVE; s++) {
            const bool act = layer ? (s >= 1) : (s < TT);
            if (!act) continue;
            const int step = layer ? s - 1 : s;
            const hf* h0h_ = g_h0h[(s + 7) & 7];
            const hf* h0l_ = g_h0l[(s + 7) & 7];
            const hf* h1h_ = g_h1h[(s + 1) & 1];
            const hf* h1l_ = g_h1l[(s + 1) & 1];
            #pragma unroll 1
            for (int sc = 0; sc < NSC; sc++) {
                if (lane == 0) {
                    if (layer == 0) {
                        if (sc == 0 && s >= 7) bar_wait(&g_ctr1, 64u * (unsigned)(s - 5));
                        if (sc == 2) bar_wait(&g_ctr0, 64u * (unsigned)(s + 1));
                    } else {
                        if (sc == 0) bar_wait(&g_ctr0, 64u * (unsigned)(s + 1));
                        if (sc == 4) bar_wait(&g_ctr1, 64u * (unsigned)(s + 1));
                    }
                }
                __syncwarp();
                mwait(mbE + pst * 8, (unsigned)pph);
                pstage(sbase + SM_RING + (unsigned)pst * RINGB, sc, layer, nb, step, lane,
                       h0h_, h0l_, h1h_, h1l_);
                cp_mbar_arrive(mbF + pst * 8);
                if (++pst == 3) { pst = 0; pph ^= 1; }
            }
        }
    } else {
        // =============== 8 COMPUTE WARPS ===============
        const int wm = wid & 1;
        const int wk = wid >> 1;
        const unsigned msk  = (unsigned)(lane & 7) << 4;
        const unsigned bsel = (unsigned)(lane & 16);
        const unsigned kb   = (((unsigned)wk << 5) | bsel) ^ msk;
        const unsigned aoff = (unsigned)((32 * wm + (lane & 15)) * 128);
        const unsigned boff = (unsigned)((((lane >> 3) & 1) * 8 + (lane & 7)) * 128);

        float cstv[2];
        float bsv[2][4];
        #pragma unroll
        for (int q = 0; q < 2; q++) {
            int pp = tid + q * NCW;
            int hc = pp & 15, bloc = pp >> 4;
            int colg = sub * 16 + hc;
            cstv[q] = c0g[(layer ? BB * HH : 0) + (nb * 32 + bloc) * HH + colg];
            const float* bih = layer ? b_ih1 : b_ih0;
            const float* bhh = layer ? b_hh1 : b_hh0;
            #pragma unroll
            for (int g = 0; g < 4; g++) bsv[q][g] = bih[g * HH + colg] + bhh[g * HH + colg];
        }

        float acc[2][4][4];
        #pragma unroll
        for (int mi = 0; mi < 2; mi++)
            #pragma unroll
            for (int nj = 0; nj < 4; nj++)
                #pragma unroll
                for (int q = 0; q < 4; q++) acc[mi][nj][q] = 0.0f;

        int csi = 0, cph = 0;
        #pragma unroll 1
        for (int s = 0; s < NWAVE; s++) {
            const bool act = layer ? (s >= 1) : (s < TT);
            if (!act) {
                if (tid == 0) bar_arrive(ctrOwn);
                continue;
            }
            const int step = layer ? s - 1 : s;

            #pragma unroll 1
            for (int sc = 0; sc < NSC; sc++) {
                mwait(mbF + csi * 8, (unsigned)cph);
                cchunk(sbase + SM_W + (unsigned)sc * 16384u,
                       sbase + SM_RING + (unsigned)csi * RINGB, acc, kb, aoff, boff);
                __syncwarp();
                if (lane == 0) mbar_arrive_cnt(mbE + csi * 8, 32);
                if (++csi == 3) { csi = 0; cph ^= 1; }
            }

            // ---- epilogue: regs -> smem exchange (per k16-plane) ----
            {
                const int tq = lane >> 2, tr2 = (lane & 3) * 2;
                float* exb = exch + wk * (64 * EXPITCH);
                #pragma unroll
                for (int mi = 0; mi < 2; mi++) {
                    #pragma unroll
                    for (int nj = 0; nj < 4; nj++) {
                        int row = 32 * wm + 16 * mi + tq;
                        int col = 8 * nj + tr2;
                        *(float2*)&exb[row * EXPITCH + col] =
                            make_float2(acc[mi][nj][0], acc[mi][nj][1]);
                        *(float2*)&exb[(row + 8) * EXPITCH + col] =
                            make_float2(acc[mi][nj][2], acc[mi][nj][3]);
                        acc[mi][nj][0] = acc[mi][nj][1] = acc[mi][nj][2] = acc[mi][nj][3] = 0.0f;
                    }
                }
            }
            asm volatile("bar.sync 1, 256;" ::: "memory");
            {
                hf* ohh = layer ? g_h1h[s & 1] : g_h0h[s & 7];
                hf* ohl = layer ? g_h1l[s & 1] : g_h0l[s & 7];
                #pragma unroll
                for (int q = 0; q < 2; q++) {
                    int pp = tid + q * NCW;
                    int hc = pp & 15, bloc = pp >> 4;
                    int colg = sub * 16 + hc;
                    int bglob = nb * 32 + bloc;
                    float gi = bsv[q][0], gf = bsv[q][1], gg = bsv[q][2], go = bsv[q][3];
                    #pragma unroll
                    for (int pl = 0; pl < 4; pl++) {
                        const float* e = exch + pl * (64 * EXPITCH);
                        gi += e[(0  + hc) * EXPITCH + bloc];
                        gf += e[(16 + hc) * EXPITCH + bloc];
                        gg += e[(32 + hc) * EXPITCH + bloc];
                        go += e[(48 + hc) * EXPITCH + bloc];
                    }
                    float iv = sig_(gi), fv = sig_(gf), gv = tanh_(gg), ov = sig_(go);
                    cstv[q] = fv * cstv[q] + iv * gv;
                    float hv = ov * tanh_(cstv[q]);
                    hf hhv = __float2half(hv);
                    ohh[bglob * HH + colg] = hhv;
                    ohl[bglob * HH + colg] = __float2half(hv - __half2float(hhv));
                    if (layer && step == TT - 1) g_h1last[bglob * HH + colg] = hv;
                }
            }
            __threadfence();
            asm volatile("bar.sync 1, 256;" ::: "memory");
            if (tid == 0) bar_arrive(ctrOwn);
        }
    }

    // completion: last CTA overall resets counters for graph replay
    __syncthreads();
    if (tid == 0) {
        unsigned old;
        asm volatile("atom.release.gpu.global.add.u32 %0, [%1], %2;"
                     : "=r"(old) : "l"(&g_done), "r"(1u) : "memory");
        if (old == NBLK - 1) {
            asm volatile("st.relaxed.gpu.global.u32 [%0], %1;" :: "l"(&g_ctr0), "r"(0u) : "memory");
            asm volatile("st.relaxed.gpu.global.u32 [%0], %1;" :: "l"(&g_ctr1), "r"(0u) : "memory");
            asm volatile("st.relaxed.gpu.global.u32 [%0], %1;" :: "l"(&g_done), "r"(0u) : "memory");
        }
    }
}

// ---------------- prep kernels ----------------
__global__ void prep_w(const float* __restrict__ Wih, const float* __restrict__ Whh,
                       hf* __restrict__ outp, int Kin, int K) {
    long long idx = (long long)blockIdx.x * blockDim.x + threadIdx.x;
    if (idx >= (long long)2048 * K) return;
    int R = (int)(idx / K), k = (int)(idx - (long long)R * K);
    int sub = R >> 6, l = R & 63;
    int g = (l >> 4) * HH + sub * 16 + (l & 15);
    float v = (k < Kin) ? Wih[(size_t)g * Kin + k] : Whh[(size_t)g * HH + (k - Kin)];
    outp[idx] = __float2half(v);
}
__global__ void prep_x(const float* __restrict__ x) {
    long long idx = (long long)blockIdx.x * blockDim.x + threadIdx.x;
    if (idx >= (long long)BB * TT * II) return;
    float v = x[idx];
    hf hi = __float2half(v);
    g_xh[idx] = hi;
    g_xl[idx] = __float2half(v - __half2float(hi));
}

// ---------------- final linear head ----------------
__global__ void fc_kernel(const float* __restrict__ W, const float* __restrict__ b,
                          float* __restrict__ out) {
    int w = (blockIdx.x * blockDim.x + threadIdx.x) >> 5;
    int lane = threadIdx.x & 31;
    int r = w >> 7, c = w & 127;
    const float* hr = g_h1last + r * HH + lane * 16;
    const float* wc = W + c * HH + lane * 16;
    float acc = 0.0f;
    #pragma unroll
    for (int k = 0; k < 16; k += 4) {
        float4 hv = *(const float4*)(hr + k);
        float4 wv = *(const float4*)(wc + k);
        acc += hv.x * wv.x + hv.y * wv.y + hv.z * wv.z + hv.w * wv.w;
    }
    #pragma unroll
    for (int off = 16; off; off >>= 1) acc += __shfl_xor_sync(~0u, acc, off);
    if (lane == 0) out[w] = acc + b[c];
}

// ---------------- launch ----------------
extern "C" void kernel_launch(void* const* d_in, const int* in_sizes, int n_in,
                              void* d_out, int out_size) {
    const float* x     = (const float*)d_in[0];
    const float* h0    = (const float*)d_in[1];
    const float* c0    = (const float*)d_in[2];
    const float* W_ih0 = (const float*)d_in[3];
    const float* W_hh0 = (const float*)d_in[4];
    const float* b_ih0 = (const float*)d_in[5];
    const float* b_hh0 = (const float*)d_in[6];
    const float* W_ih1 = (const float*)d_in[7];
    const float* W_hh1 = (const float*)d_in[8];
    const float* b_ih1 = (const float*)d_in[9];
    const float* b_hh1 = (const float*)d_in[10];
    const float* W_fc  = (const float*)d_in[11];
    const float* b_fc  = (const float*)d_in[12];

    hf *w0, *w1;
    cudaGetSymbolAddress((void**)&w0, g_w0);
    cudaGetSymbolAddress((void**)&w1, g_w1);

    prep_w<<<(2048 * K0 + 255) / 256, 256>>>(W_ih0, W_hh0, w0, II, K0);
    prep_w<<<(2048 * K1 + 255) / 256, 256>>>(W_ih1, W_hh1, w1, HH, K1);
    prep_x<<<(BB * TT * II + 255) / 256, 256>>>(x);

    cudaFuncSetAttribute((const void*)lstm_mma_kernel,
                         cudaFuncAttributeMaxDynamicSharedMemorySize, SMEM_TOTAL);
    lstm_mma_kernel<<<NBLK, NTHR, SMEM_TOTAL>>>(b_ih0, b_hh0, b_ih1, b_hh1, h0, c0);

    fc_kernel<<<(BB * CC * 32) / 256, 256>>>(W_fc, b_fc, (float*)d_out);
}

// round 17
// speedup vs baseline: 2.6631x; 2.6631x over previous
#include <cuda_runtime.h>
#include <cuda_fp16.h>
#include <math.h>

typedef __half hf;

#define BB 64
#define TT 512
#define II 256
#define HH 512
#define CC 128

#define NBLK 128
#define NTHR 256
#define NWAVE (TT + 1)   // 513

#define K0 768
#define K1 1024
#define NSC0 6
#define NSC1 8

// smem layout (bytes)
#define SM_W    0                 // resident W: up to 16 subtiles x 8KB = 128KB
#define SM_RING 131072            // 3 x 16KB X ring: [t0 Xh 4K|Xl 4K][t1 Xh 4K|Xl 4K]
#define RINGB   16384
#define SM_EXCH 180224            // 4 planes x 64 x EXPITCH x 4B = 34816
#define EXPITCH 34
#define SMEM_TOTAL 215040

#define SWZ(o) ((o) ^ (((o) >> 3) & 0x70))

// ---------------- device scratch ----------------
__device__ __align__(256) hf g_w0[2048 * K0];
__device__ __align__(256) hf g_w1[2048 * K1];
__device__ __align__(256) hf g_xh[(size_t)BB * TT * II], g_xl[(size_t)BB * TT * II];
__device__ __align__(256) hf g_h0h[8][BB * HH], g_h0l[8][BB * HH];   // 8-deep ring
__device__ __align__(256) hf g_h1h[2][BB * HH], g_h1l[2][BB * HH];
__device__ float g_h1last[BB * HH];
__device__ unsigned g_ctr0, g_ctr1, g_done;   // zero-init; reset at kernel end

// ---------------- primitives ----------------
__device__ __forceinline__ void cp16(unsigned saddr, const void* g) {
    asm volatile("cp.async.cg.shared.global [%0], [%1], 16;\n" :: "r"(saddr), "l"(g) : "memory");
}
__device__ __forceinline__ void cp_commit() {
    asm volatile("cp.async.commit_group;\n" ::: "memory");
}
template <int N> __device__ __forceinline__ void cp_wait() {
    asm volatile("cp.async.wait_group %0;\n" :: "n"(N) : "memory");
}
__device__ __forceinline__ void bar_arrive(unsigned* ctr) {
    unsigned old;
    asm volatile("atom.release.gpu.global.add.u32 %0, [%1], %2;"
                 : "=r"(old) : "l"(ctr), "r"(1u) : "memory");
}
__device__ __forceinline__ void bar_wait(unsigned* ctr, unsigned target) {
    unsigned v;
    do {
        asm volatile("ld.acquire.gpu.global.u32 %0, [%1];" : "=r"(v) : "l"(ctr) : "memory");
    } while (v < target);
}
__device__ __forceinline__ float sig_(float x)  { return 1.0f / (1.0f + __expf(-x)); }
__device__ __forceinline__ float tanh_(float x) { return 2.0f / (1.0f + __expf(-2.0f * x)) - 1.0f; }

__device__ __forceinline__ void ldsm4(unsigned* r, unsigned addr) {
    asm volatile("ldmatrix.sync.aligned.m8n8.x4.shared.b16 {%0,%1,%2,%3}, [%4];"
                 : "=r"(r[0]), "=r"(r[1]), "=r"(r[2]), "=r"(r[3]) : "r"(addr));
}
__device__ __forceinline__ void mma16816(float* c, const unsigned* a, unsigned b0, unsigned b1) {
    asm volatile(
        "mma.sync.aligned.m16n8k16.row.col.f32.f16.f16.f32 "
        "{%0,%1,%2,%3}, {%4,%5,%6,%7}, {%8,%9}, {%0,%1,%2,%3};"
        : "+f"(c[0]), "+f"(c[1]), "+f"(c[2]), "+f"(c[3])
        : "r"(a[0]), "r"(a[1]), "r"(a[2]), "r"(a[3]), "r"(b0), "r"(b1));
}

// ---------------- staging: one K=128 superchunk of X only (1024 granules) -------------
__device__ __forceinline__ void stage(
    unsigned dst, int sc, int layer, int nb, int step, int tid,
    const hf* h0h_, const hf* h0l_, const hf* h1h_, const hf* h1l_)
{
    #pragma unroll
    for (int q = 0; q < 4; q++) {
        int idx = tid + q * NTHR;
        int t = idx >> 9, rem9 = idx & 511;
        int plane = rem9 >> 8, rem = rem9 & 255;
        int row = rem >> 3, j = rem & 7;
        int rg = nb * 32 + row;
        int k = sc * 128 + t * 64 + j * 8;
        const hf* src;
        if (layer == 0)
            src = (k < II) ? (plane ? g_xl : g_xh) + ((size_t)rg * TT + step) * II + k
                           : (plane ? h0l_ : h0h_) + rg * HH + (k - II);
        else
            src = (k < HH) ? (plane ? h0l_ : h0h_) + rg * HH + k
                           : (plane ? h1l_ : h1h_) + rg * HH + (k - HH);
        cp16(dst + (unsigned)t * 8192u + (unsigned)plane * 4096u
             + SWZ((unsigned)(row * 128 + j * 16)), src);
    }
    cp_commit();
}

// ---------------- tensor compute: one superchunk (K=128), m32 x n32, 2 fp16 terms ------
__device__ __forceinline__ void cchunk(
    unsigned wch, unsigned xch, float acc[2][4][4],
    unsigned kb, unsigned aoff, unsigned boff)
{
    #pragma unroll
    for (int t = 0; t < 2; t++) {
        const unsigned wb = wch + (unsigned)t * 8192u;
        const unsigned xb = xch + (unsigned)t * 8192u;
        unsigned a0[4], a1[4], b0h[4], b1h[4], b0l[4], b1l[4];
        ldsm4(a0, wb + aoff + kb);
        ldsm4(a1, wb + aoff + 2048u + kb);
        ldsm4(b0h, xb + boff + kb);
        ldsm4(b1h, xb + boff + 2048u + kb);
        ldsm4(b0l, xb + 4096u + boff + kb);
        ldsm4(b1l, xb + 4096u + 2048u + boff + kb);
        #pragma unroll
        for (int mi = 0; mi < 2; mi++) {
            const unsigned* a = mi ? a1 : a0;
            mma16816(acc[mi][0], a, b0h[0], b0h[2]);
            mma16816(acc[mi][1], a, b0h[1], b0h[3]);
            mma16816(acc[mi][2], a, b1h[0], b1h[2]);
            mma16816(acc[mi][3], a, b1h[1], b1h[3]);
            mma16816(acc[mi][0], a, b0l[0], b0l[2]);
            mma16816(acc[mi][1], a, b0l[1], b0l[3]);
            mma16816(acc[mi][2], a, b1l[0], b1l[2]);
            mma16816(acc[mi][3], a, b1l[1], b1l[3]);
        }
    }
}

// ---------------- main persistent kernel ----------------
__global__ void __launch_bounds__(NTHR, 1) lstm_mma_kernel(
    const float* __restrict__ b_ih0, const float* __restrict__ b_hh0,
    const float* __restrict__ b_ih1, const float* __restrict__ b_hh1,
    const float* __restrict__ h0g, const float* __restrict__ c0g)
{
    extern __shared__ char smem[];
    const unsigned sbase = (unsigned)__cvta_generic_to_shared(smem);
    float* exch = (float*)(smem + SM_EXCH);

    const int tid = threadIdx.x;
    const int lane = tid & 31, wid = tid >> 5;
    const int blk = blockIdx.x;
    const int layer = blk >> 6;            // 0..1
    const int sub = (blk >> 1) & 31;       // gate sub-block (16 h-cols)
    const int nb  = blk & 1;               // batch half
    const int wm = wid & 1;                // m32 tile
    const int wk = wid >> 1;               // k16-step within k64 subtile (0..3)
    const int K = layer ? K1 : K0;
    const int NSC = layer ? NSC1 : NSC0;
    const hf* w = layer ? g_w1 : g_w0;
    unsigned* ctrOwn = layer ? &g_ctr1 : &g_ctr0;

    // ldmatrix per-lane constants (SW128 swizzle mask from row%8)
    const unsigned msk  = (unsigned)(lane & 7) << 4;
    const unsigned bsel = (unsigned)(lane & 16);
    const unsigned kb   = (((unsigned)wk << 5) | bsel) ^ msk;
    const unsigned aoff = (unsigned)((32 * wm + (lane & 15)) * 128);
    const unsigned boff = (unsigned)((((lane >> 3) & 1) * 8 + (lane & 7)) * 128);

    // ---- prologue: W resident load (once) + h/c init ----
    {
        const int nsub = K >> 6;
        for (int idx = tid; idx < nsub * 512; idx += NTHR) {
            int s64 = idx >> 9, rem = idx & 511, row = rem >> 3, j = rem & 7;
            const hf* src = w + (size_t)(sub * 64 + row) * K + s64 * 64 + j * 8;
            cp16(sbase + SM_W + (unsigned)s64 * 8192u + SWZ((unsigned)(row * 128 + j * 16)), src);
        }
        cp_commit();
        cp_wait<0>();
        int i = blk * 256 + tid;
        float v0 = h0g[i];
        hf a = __float2half(v0);
        g_h0h[7][i] = a; g_h0l[7][i] = __float2half(v0 - __half2float(a));
        float v1 = h0g[BB * HH + i];
        hf b = __float2half(v1);
        g_h1h[0][i] = b; g_h1l[0][i] = __float2half(v1 - __half2float(b));
    }

    // epilogue role: two (h-col, batch) pairs per thread
    float cst[2];
    float bsv[2][4];
    #pragma unroll
    for (int q = 0; q < 2; q++) {
        int pp = tid + q * NTHR;
        int hc = pp & 15, bloc = pp >> 4;
        int colg = sub * 16 + hc;
        cst[q] = c0g[(layer ? BB * HH : 0) + (nb * 32 + bloc) * HH + colg];
        const float* bih = layer ? b_ih1 : b_ih0;
        const float* bhh = layer ? b_hh1 : b_hh0;
        #pragma unroll
        for (int g = 0; g < 4; g++) bsv[q][g] = bih[g * HH + colg] + bhh[g * HH + colg];
    }

    __threadfence();
    __syncthreads();
    if (tid == 0) bar_arrive(ctrOwn);      // init publish

    float acc[2][4][4];
    #pragma unroll
    for (int mi = 0; mi < 2; mi++)
        #pragma unroll
        for (int nj = 0; nj < 4; nj++)
            #pragma unroll
            for (int q = 0; q < 4; q++) acc[mi][nj][q] = 0.0f;

    #pragma unroll 1
    for (int s = 0; s < NWAVE; s++) {
        const bool active = layer ? (s >= 1) : (s < TT);
        if (!active) {
            if (tid == 0) bar_arrive(ctrOwn);
            continue;
        }
        const int step = layer ? s - 1 : s;
        const unsigned wt = 64u * (unsigned)(s + 1);
        const hf* h0h_ = g_h0h[(s + 7) & 7];     // h0(s-1)
        const hf* h0l_ = g_h0l[(s + 7) & 7];
        const hf* h1h_ = g_h1h[(s + 1) & 1];     // h1(step-1)
        const hf* h1l_ = g_h1l[(s + 1) & 1];

        if (layer) {
            // h0(s-1) needed from superchunk 0: L0 runs ahead, usually satisfied
            if (tid == 0) bar_wait(&g_ctr0, wt);
            __syncthreads();
        } else if (s >= 7) {
            // ring safety: h0(s) write clobbers h0(s-8); L1 must be done wave s-7
            if (tid == 0) bar_wait(&g_ctr1, 64u * (unsigned)(s - 5));
            __syncthreads();
        }

        stage(sbase + SM_RING + 0u * RINGB, 0, layer, nb, step, tid, h0h_, h0l_, h1h_, h1l_);
        stage(sbase + SM_RING + 1u * RINGB, 1, layer, nb, step, tid, h0h_, h0l_, h1h_, h1l_);

        #pragma unroll 1
        for (int sc = 0; sc < NSC; sc++) {
            if (sc + 1 < NSC) cp_wait<1>(); else cp_wait<0>();
            // gates before staging the first h-dependent superchunk
            if (layer == 0 && sc == 0) {          // stage(2) reads h0(s-1)
                if (tid == 0) bar_wait(&g_ctr0, wt);
            }
            if (layer == 1 && sc == 2) {          // stage(4) reads h1(step-1)
                if (tid == 0) bar_wait(&g_ctr1, wt);
            }
            __syncthreads();
            if (sc + 2 < NSC)
                stage(sbase + SM_RING + (unsigned)((sc + 2) % 3) * RINGB, sc + 2,
                      layer, nb, step, tid, h0h_, h0l_, h1h_, h1l_);
            cchunk(sbase + SM_W + (unsigned)sc * 16384u,
                   sbase + SM_RING + (unsigned)(sc % 3) * RINGB, acc, kb, aoff, boff);
        }

        // ---- epilogue: regs -> smem exchange (per k16-plane) ----
        {
            const int tq = lane >> 2, tr2 = (lane & 3) * 2;
            float* exb = exch + wk * (64 * EXPITCH);
            #pragma unroll
            for (int mi = 0; mi < 2; mi++) {
                #pragma unroll
                for (int nj = 0; nj < 4; nj++) {
                    int row = 32 * wm + 16 * mi + tq;
                    int col = 8 * nj + tr2;
                    *(float2*)&exb[row * EXPITCH + col] =
                        make_float2(acc[mi][nj][0], acc[mi][nj][1]);
                    *(float2*)&exb[(row + 8) * EXPITCH + col] =
                        make_float2(acc[mi][nj][2], acc[mi][nj][3]);
                    acc[mi][nj][0] = acc[mi][nj][1] = acc[mi][nj][2] = acc[mi][nj][3] = 0.0f;
                }
            }
        }
        __syncthreads();
        {
            hf* ohh = layer ? g_h1h[s & 1] : g_h0h[s & 7];
            hf* ohl = layer ? g_h1l[s & 1] : g_h0l[s & 7];
            #pragma unroll
            for (int q = 0; q < 2; q++) {
                int pp = tid + q * NTHR;
                int hc = pp & 15, bloc = pp >> 4;
                int colg = sub * 16 + hc;
                int bglob = nb * 32 + bloc;
                float gi = bsv[q][0], gf = bsv[q][1], gg = bsv[q][2], go = bsv[q][3];
                #pragma unroll
                for (int pl = 0; pl < 4; pl++) {
                    const float* e = exch + pl * (64 * EXPITCH);
                    gi += e[(0  + hc) * EXPITCH + bloc];
                    gf += e[(16 + hc) * EXPITCH + bloc];
                    gg += e[(32 + hc) * EXPITCH + bloc];
                    go += e[(48 + hc) * EXPITCH + bloc];
                }
                float iv = sig_(gi), fv = sig_(gf), gv = tanh_(gg), ov = sig_(go);
                cst[q] = fv * cst[q] + iv * gv;
                float hv = ov * tanh_(cst[q]);
                hf hhv = __float2half(hv);
                ohh[bglob * HH + colg] = hhv;
                ohl[bglob * HH + colg] = __float2half(hv - __half2float(hhv));
                if (layer && step == TT - 1) g_h1last[bglob * HH + colg] = hv;
            }
        }
        __threadfence();
        __syncthreads();
        if (tid == 0) bar_arrive(ctrOwn);
    }

    // completion: last CTA overall resets counters for graph replay
    __syncthreads();
    if (tid == 0) {
        unsigned old;
        asm volatile("atom.release.gpu.global.add.u32 %0, [%1], %2;"
                     : "=r"(old) : "l"(&g_done), "r"(1u) : "memory");
        if (old == NBLK - 1) {
            asm volatile("st.relaxed.gpu.global.u32 [%0], %1;" :: "l"(&g_ctr0), "r"(0u) : "memory");
            asm volatile("st.relaxed.gpu.global.u32 [%0], %1;" :: "l"(&g_ctr1), "r"(0u) : "memory");
            asm volatile("st.relaxed.gpu.global.u32 [%0], %1;" :: "l"(&g_done), "r"(0u) : "memory");
        }
    }
}

// ---------------- prep kernels ----------------
__global__ void prep_w(const float* __restrict__ Wih, const float* __restrict__ Whh,
                       hf* __restrict__ outp, int Kin, int K) {
    long long idx = (long long)blockIdx.x * blockDim.x + threadIdx.x;
    if (idx >= (long long)2048 * K) return;
    int R = (int)(idx / K), k = (int)(idx - (long long)R * K);
    int sub = R >> 6, l = R & 63;
    int g = (l >> 4) * HH + sub * 16 + (l & 15);
    float v = (k < Kin) ? Wih[(size_t)g * Kin + k] : Whh[(size_t)g * HH + (k - Kin)];
    outp[idx] = __float2half(v);
}
__global__ void prep_x(const float* __restrict__ x) {
    long long idx = (long long)blockIdx.x * blockDim.x + threadIdx.x;
    if (idx >= (long long)BB * TT * II) return;
    float v = x[idx];
    hf hi = __float2half(v);
    g_xh[idx] = hi;
    g_xl[idx] = __float2half(v - __half2float(hi));
}

// ---------------- final linear head ----------------
__global__ void fc_kernel(const float* __restrict__ W, const float* __restrict__ b,
                          float* __restrict__ out) {
    int w = (blockIdx.x * blockDim.x + threadIdx.x) >> 5;
    int lane = threadIdx.x & 31;
    int r = w >> 7, c = w & 127;
    const float* hr = g_h1last + r * HH + lane * 16;
    const float* wc = W + c * HH + lane * 16;
    float acc = 0.0f;
    #pragma unroll
    for (int k = 0; k < 16; k += 4) {
        float4 hv = *(const float4*)(hr + k);
        float4 wv = *(const float4*)(wc + k);
        acc += hv.x * wv.x + hv.y * wv.y + hv.z * wv.z + hv.w * wv.w;
    }
    #pragma unroll
    for (int off = 16; off; off >>= 1) acc += __shfl_xor_sync(~0u, acc, off);
    if (lane == 0) out[w] = acc + b[c];
}

// ---------------- launch ----------------
extern "C" void kernel_launch(void* const* d_in, const int* in_sizes, int n_in,
                              void* d_out, int out_size) {
    const float* x     = (const float*)d_in[0];
    const float* h0    = (const float*)d_in[1];
    const float* c0    = (const float*)d_in[2];
    const float* W_ih0 = (const float*)d_in[3];
    const float* W_hh0 = (const float*)d_in[4];
    const float* b_ih0 = (const float*)d_in[5];
    const float* b_hh0 = (const float*)d_in[6];
    const float* W_ih1 = (const float*)d_in[7];
    const float* W_hh1 = (const float*)d_in[8];
    const float* b_ih1 = (const float*)d_in[9];
    const float* b_hh1 = (const float*)d_in[10];
    const float* W_fc  = (const float*)d_in[11];
    const float* b_fc  = (const float*)d_in[12];

    hf *w0, *w1;
    cudaGetSymbolAddress((void**)&w0, g_w0);
    cudaGetSymbolAddress((void**)&w1, g_w1);

    prep_w<<<(2048 * K0 + 255) / 256, 256>>>(W_ih0, W_hh0, w0, II, K0);
    prep_w<<<(2048 * K1 + 255) / 256, 256>>>(W_ih1, W_hh1, w1, HH, K1);
    prep_x<<<(BB * TT * II + 255) / 256, 256>>>(x);

    cudaFuncSetAttribute((const void*)lstm_mma_kernel,
                         cudaFuncAttributeMaxDynamicSharedMemorySize, SMEM_TOTAL);
    lstm_mma_kernel<<<NBLK, NTHR, SMEM_TOTAL>>>(b_ih0, b_hh0, b_ih1, b_hh1, h0, c0);

    fc_kernel<<<(BB * CC * 32) / 256, 256>>>(W_fc, b_fc, (float*)d_out);
}